// round 13
// baseline (speedup 1.0000x reference)
#include <cuda_runtime.h>
#include <math.h>
#include <cstdint>

static constexpr int B_DIM = 8192;
static constexpr int N_PTS = 1024;
static constexpr int THREADS = 256;
static constexpr int GRID = 888;            // 148 SMs * 6 CTAs/SM
static constexpr int WARPS = THREADS / 32;
static constexpr int ROW_BYTES = N_PTS * 3 * 4;        // 12288 B per row
static constexpr int SEG_BYTES = ROW_BYTES / WARPS;    // 1536 B per warp
static constexpr int SEG_CHUNKS = SEG_BYTES / 16;      // 96 float4 per warp

// Allocation-free scratch (__device__ globals per harness rules).
__device__ double g_acc;
__device__ unsigned int g_ticket;
__device__ float g_D[B_DIM * 12];           // D padded to 12 floats/row (3x float4)

__device__ __forceinline__ float fast_sqrt(float x) {
    float r;
    asm("sqrt.approx.f32 %0, %1;" : "=f"(r) : "f"(x));
    return r;
}

__device__ __forceinline__ void euler_to_matrix(float a, float b, float c, float* R) {
    const float sa = sinf(a), ca = cosf(a);
    const float sb = sinf(b), cb = cosf(b);
    const float sc = sinf(c), cc = cosf(c);
    // R = Rx(a) * Ry(b) * Rz(c)
    R[0] = cb * cc;
    R[1] = -cb * sc;
    R[2] = sb;
    R[3] = ca * sc + sa * sb * cc;
    R[4] = ca * cc - sa * sb * sc;
    R[5] = -sa * cb;
    R[6] = sa * sc - ca * sb * cc;
    R[7] = sa * cc + ca * sb * sc;
    R[8] = ca * cb;
}

// Kernel 1: per-row trig + matrix difference (8192 parallel threads) + state reset.
__global__ __launch_bounds__(256)
void precompute_kernel(const float* __restrict__ pred,
                       const float* __restrict__ mode,
                       const float* __restrict__ gt) {
    const int b = blockIdx.x * blockDim.x + threadIdx.x;
    if (b == 0) { g_acc = 0.0; g_ticket = 0u; }
    if (b >= B_DIM) return;

    const float m1 = pred[b * 4 + 0];
    const float m2 = pred[b * 4 + 1];
    const float m3 = pred[b * 4 + 2];
    const float m4 = pred[b * 4 + 3];
    const float sgn = (mode[b] > 0.5f) ? 1.0f : -1.0f;
    const float denom = m1 * m1 + m2 * m2 + m3 * m3;
    const float e2 = sgn * asinf(sqrtf(m3 * m3 / denom));
    const float se2 = sinf(e2);
    const float ce2 = cosf(e2);
    const float e3 = atan2f(m4, m3 / (se2 + 1e-9f));
    const float tmp = ce2 * cosf(e3);
    const float e1 = atan2f(m2 / tmp, m1 / tmp);
    // (ref's +2pi wrap of euler3 only shifts by a full period; sin/cos unchanged)

    float Rp[9], Rg[9];
    euler_to_matrix(e1, e2, e3, Rp);
    euler_to_matrix(gt[b * 3 + 0], gt[b * 3 + 1], gt[b * 3 + 2], Rg);

    float4* dst = (float4*)(g_D + b * 12);  // 48B row stride, 16B aligned
    dst[0] = make_float4(Rp[0] - Rg[0], Rp[1] - Rg[1], Rp[2] - Rg[2], Rp[3] - Rg[3]);
    dst[1] = make_float4(Rp[4] - Rg[4], Rp[5] - Rg[5], Rp[6] - Rg[6], Rp[7] - Rg[7]);
    dst[2] = make_float4(Rp[8] - Rg[8], 0.0f, 0.0f, 0.0f);
}

// Kernel 2: persistent streaming with per-warp cp.async double buffering.
// Coalesced 16B cp.async (L1 bypass, wavefront-minimal), LDS consume, approx sqrt.
__global__ __launch_bounds__(THREADS, 6)
void add_loss_kernel(const float* __restrict__ point, float* __restrict__ out) {
    __shared__ float4 buf[2][WARPS][SEG_CHUNKS];   // 2 x 12 KB
    __shared__ float warp_sums[WARPS];

    const int t = threadIdx.x;
    const int w = t >> 5;
    const int l = t & 31;
    float acc = 0.0f;

    const char* src = (const char*)point + (size_t)blockIdx.x * ROW_BYTES
                      + (size_t)w * SEG_BYTES + (size_t)l * 16;
    const size_t step = (size_t)GRID * ROW_BYTES;
    const float4* __restrict__ dptr = (const float4*)g_D + (size_t)blockIdx.x * 3;
    const size_t dstep = (size_t)GRID * 3;

    // Per-warp stage: 3 coalesced 16B cp.async into buffer pp.
    auto stage = [&](int pp, const char* s) {
        uint32_t dst = (uint32_t)__cvta_generic_to_shared(&buf[pp][w][l]);
        asm volatile(
            "cp.async.cg.shared.global [%0], [%1], 16;\n\t"
            "cp.async.cg.shared.global [%2], [%3], 16;\n\t"
            "cp.async.cg.shared.global [%4], [%5], 16;\n\t"
            "cp.async.commit_group;\n\t"
            :: "r"(dst),            "l"(s),
               "r"(dst + 32 * 16), "l"(s + 32 * 16),
               "r"(dst + 64 * 16), "l"(s + 64 * 16)
            : "memory");
    };

    int b = blockIdx.x;
    int pp = 0;
    if (b < B_DIM) stage(0, src);

    #pragma unroll 1
    while (b < B_DIM) {
        const int nb = b + GRID;
        // D loads (L2-hot broadcast) issued before the wait — overlapped.
        const float4 D0 = dptr[0];
        const float4 D1 = dptr[1];
        const float4 D2 = dptr[2];

        if (nb < B_DIM) {
            stage(pp ^ 1, src + step);                      // prefetch next row
            asm volatile("cp.async.wait_group 1;" ::: "memory");
        } else {
            asm volatile("cp.async.wait_group 0;" ::: "memory");
        }
        __syncwarp();

        // Consume lane-private triples (LDS.128 stride 48B: conflict-free phases).
        const float4 av = buf[pp][w][3 * l + 0];
        const float4 bv = buf[pp][w][3 * l + 1];
        const float4 cv = buf[pp][w][3 * l + 2];

        const float d00 = D0.x, d01 = D0.y, d02 = D0.z;
        const float d10 = D0.w, d11 = D1.x, d12 = D1.y;
        const float d20 = D1.z, d21 = D1.w, d22 = D2.x;

        const float px[4] = {av.x, av.w, bv.z, cv.y};
        const float py[4] = {av.y, bv.x, bv.w, cv.z};
        const float pz[4] = {av.z, bv.y, cv.x, cv.w};
        #pragma unroll
        for (int i = 0; i < 4; i++) {
            const float q0 = fmaf(px[i], d00, fmaf(py[i], d10, pz[i] * d20));
            const float q1 = fmaf(px[i], d01, fmaf(py[i], d11, pz[i] * d21));
            const float q2 = fmaf(px[i], d02, fmaf(py[i], d12, pz[i] * d22));
            acc += fast_sqrt(fmaf(q0, q0, fmaf(q1, q1, q2 * q2)));
        }
        __syncwarp();   // all lanes done with buf[pp] before it is restaged

        pp ^= 1;
        b = nb;
        src += step;
        dptr += dstep;
    }

    // One reduce + one atomic per CTA.
    #pragma unroll
    for (int off = 16; off > 0; off >>= 1)
        acc += __shfl_xor_sync(0xffffffffu, acc, off);
    if (l == 0) warp_sums[w] = acc;
    __syncthreads();

    if (t == 0) {
        float s = 0.0f;
        #pragma unroll
        for (int i = 0; i < WARPS; i++) s += warp_sums[i];
        atomicAdd(&g_acc, (double)s);
        __threadfence();
        const unsigned int ticket = atomicAdd(&g_ticket, 1u);
        if (ticket == (unsigned int)(gridDim.x - 1)) {
            __threadfence();
            const double total = atomicAdd(&g_acc, 0.0);
            out[0] = (float)(total * (1.0 / ((double)B_DIM * (double)N_PTS)));
        }
    }
}

extern "C" void kernel_launch(void* const* d_in, const int* in_sizes, int n_in,
                              void* d_out, int out_size) {
    const float* pred  = (const float*)d_in[0];   // (8192, 4)
    const float* mode  = (const float*)d_in[1];   // (8192,)
    const float* gt    = (const float*)d_in[2];   // (8192, 3)
    const float* point = (const float*)d_in[3];   // (8192, 1024, 3)
    float* out = (float*)d_out;

    precompute_kernel<<<B_DIM / 256, 256>>>(pred, mode, gt);
    add_loss_kernel<<<GRID, THREADS>>>(point, out);
}

// round 14
// speedup vs baseline: 1.2117x; 1.2117x over previous
#include <cuda_runtime.h>
#include <math.h>

static constexpr int B_DIM = 8192;
static constexpr int N_PTS = 1024;
static constexpr int THREADS = 256;
static constexpr int GRID = 888;               // 148 SMs * 6 CTAs/SM
static constexpr int MAX_ROWS = (B_DIM + GRID - 1) / GRID;   // 10 rows per CTA max

// Allocation-free scratch (__device__ globals per harness rules).
__device__ double g_acc;            // zero at load; self-reset by last block
__device__ unsigned int g_ticket;   // ditto

__device__ __forceinline__ float fast_sqrt(float x) {
    float r;
    asm("sqrt.approx.f32 %0, %1;" : "=f"(r) : "f"(x));
    return r;
}

__device__ __forceinline__ void euler_to_matrix(float a, float b, float c, float* R) {
    const float sa = sinf(a), ca = cosf(a);
    const float sb = sinf(b), cb = cosf(b);
    const float sc = sinf(c), cc = cosf(c);
    // R = Rx(a) * Ry(b) * Rz(c)
    R[0] = cb * cc;
    R[1] = -cb * sc;
    R[2] = sb;
    R[3] = ca * sc + sa * sb * cc;
    R[4] = ca * cc - sa * sb * sc;
    R[5] = -sa * cb;
    R[6] = sa * sc - ca * sb * cc;
    R[7] = sa * cc + ca * sb * sc;
    R[8] = ca * cb;
}

__device__ __forceinline__ void compute_D(int b,
                                          const float* __restrict__ pred,
                                          const float* __restrict__ mode,
                                          const float* __restrict__ gt,
                                          float* __restrict__ Dout /*12 floats*/) {
    const float m1 = pred[b * 4 + 0];
    const float m2 = pred[b * 4 + 1];
    const float m3 = pred[b * 4 + 2];
    const float m4 = pred[b * 4 + 3];
    const float sgn = (mode[b] > 0.5f) ? 1.0f : -1.0f;
    const float denom = m1 * m1 + m2 * m2 + m3 * m3;
    const float e2 = sgn * asinf(sqrtf(m3 * m3 / denom));
    const float se2 = sinf(e2);
    const float ce2 = cosf(e2);
    const float e3 = atan2f(m4, m3 / (se2 + 1e-9f));
    const float tmp = ce2 * cosf(e3);
    const float e1 = atan2f(m2 / tmp, m1 / tmp);
    // (ref's +2pi wrap of euler3 only shifts by a full period; sin/cos unchanged)

    float Rp[9], Rg[9];
    euler_to_matrix(e1, e2, e3, Rp);
    euler_to_matrix(gt[b * 3 + 0], gt[b * 3 + 1], gt[b * 3 + 2], Rg);
    #pragma unroll
    for (int i = 0; i < 9; i++) Dout[i] = Rp[i] - Rg[i];
    Dout[9] = Dout[10] = Dout[11] = 0.0f;
}

// Single fused persistent kernel. Prologue: threads 0..MAX_ROWS-1 each compute
// one row's D matrix into shared (parallel trig, once per CTA). Main loop: R12's
// bench-best streaming structure with D served from shared.
__global__ __launch_bounds__(THREADS, 6)
void add_loss_kernel(const float* __restrict__ pred,
                     const float* __restrict__ mode,
                     const float* __restrict__ gt,
                     const float* __restrict__ point,
                     float* __restrict__ out) {
    __shared__ float Dsh[MAX_ROWS][12];       // 48B rows, float4-aligned
    __shared__ float warp_sums[THREADS / 32];

    const int t = threadIdx.x;

    // Distributed trig: one thread per row owned by this CTA (~10 threads busy,
    // one trig chain each, fully parallel; ~700 cycles once per CTA lifetime).
    if (t < MAX_ROWS) {
        const int b = blockIdx.x + t * GRID;
        if (b < B_DIM) compute_D(b, pred, mode, gt, Dsh[t]);
    }
    __syncthreads();

    float acc = 0.0f;

    // Incremental pointer (cuts per-iteration 64-bit IMADs).
    const float4* __restrict__ p = (const float4*)(point)
        + (size_t)blockIdx.x * (N_PTS * 3 / 4) + 3 * t;
    const size_t p_step = (size_t)GRID * (N_PTS * 3 / 4);

    int k = 0;
    #pragma unroll 1
    for (int b = blockIdx.x; b < B_DIM; b += GRID, p += p_step, k++) {
        // 3 point LDG.128 (the only global traffic in the loop).
        const float4 av = p[0];
        const float4 bv = p[1];
        const float4 cv = p[2];

        // D from shared: 3 broadcast LDS.128.
        const float4* Drow = (const float4*)Dsh[k];
        const float4 D0 = Drow[0];
        const float4 D1 = Drow[1];
        const float4 D2 = Drow[2];

        const float d00 = D0.x, d01 = D0.y, d02 = D0.z;
        const float d10 = D0.w, d11 = D1.x, d12 = D1.y;
        const float d20 = D1.z, d21 = D1.w, d22 = D2.x;

        const float px[4] = {av.x, av.w, bv.z, cv.y};
        const float py[4] = {av.y, bv.x, bv.w, cv.z};
        const float pz[4] = {av.z, bv.y, cv.x, cv.w};
        #pragma unroll
        for (int i = 0; i < 4; i++) {
            const float q0 = fmaf(px[i], d00, fmaf(py[i], d10, pz[i] * d20));
            const float q1 = fmaf(px[i], d01, fmaf(py[i], d11, pz[i] * d21));
            const float q2 = fmaf(px[i], d02, fmaf(py[i], d12, pz[i] * d22));
            acc += fast_sqrt(fmaf(q0, q0, fmaf(q1, q1, q2 * q2)));
        }
    }

    // One reduce + one atomic per CTA.
    #pragma unroll
    for (int off = 16; off > 0; off >>= 1)
        acc += __shfl_xor_sync(0xffffffffu, acc, off);
    if ((t & 31) == 0) warp_sums[t >> 5] = acc;
    __syncthreads();

    if (t == 0) {
        float s = 0.0f;
        #pragma unroll
        for (int w = 0; w < THREADS / 32; w++) s += warp_sums[w];
        atomicAdd(&g_acc, (double)s);
        __threadfence();
        const unsigned int ticket = atomicAdd(&g_ticket, 1u);
        if (ticket == (unsigned int)(gridDim.x - 1)) {
            __threadfence();
            const double total = atomicAdd(&g_acc, 0.0);
            out[0] = (float)(total * (1.0 / ((double)B_DIM * (double)N_PTS)));
            // Self-reset for next graph replay (stream-ordered after all atomics).
            g_acc = 0.0;
            g_ticket = 0u;
        }
    }
}

extern "C" void kernel_launch(void* const* d_in, const int* in_sizes, int n_in,
                              void* d_out, int out_size) {
    const float* pred  = (const float*)d_in[0];   // (8192, 4)
    const float* mode  = (const float*)d_in[1];   // (8192,)
    const float* gt    = (const float*)d_in[2];   // (8192, 3)
    const float* point = (const float*)d_in[3];   // (8192, 1024, 3)
    float* out = (float*)d_out;

    add_loss_kernel<<<GRID, THREADS>>>(pred, mode, gt, point, out);
}